// round 6
// baseline (speedup 1.0000x reference)
#include <cuda_runtime.h>
#include <stdint.h>

#define OUTF 8192
#define INF  8192
#define GROUPS 256            // groups of 32 in-features (3 packed words each)
#define KS 64                 // split-K factor
#define GPB (GROUPS / KS)     // 4 groups per block
#define TPB 128
#define COLS_PER_THREAD 4
#define COLS_PER_BLOCK (TPB * COLS_PER_THREAD)   // 512
#define NCB (OUTF / COLS_PER_BLOCK)              // 16
#define ROWSTRIDE4 (OUTF / 4)                    // uint4 row stride

// parity mask over SOURCE index (mod 32): "hi" member of an extraction pair,
// whose x is pre-scaled by 1/8 at staging (exact power of two).
#define HI_MASK 0xAA9552AAu

// split-K partial dot products: partial[k][n] = sum over K-slice k of x*q
__device__ float g_partial[KS * OUTF];
// per-stripe completion counters (zero-init; reducer resets to 0 each launch)
__device__ int g_count[NCB];

__device__ __forceinline__ float dq3(unsigned v) {
    return __uint_as_float(0x4B000000u | v) - 8388608.0f;
}

// One extraction pair, fully packed:
//   lo = (s & 7)  | 0x4B000000   -> 2^23 + v_lo
//   hi = (s & 56) | 0x4B000000   -> 2^23 + 8*v_hi   (x_hi pre-scaled by 1/8)
// then one ADD2 (de-bias both lanes) + one FFMA2 (both products into acc).
__device__ __forceinline__ void dqpair(unsigned s, unsigned long long xp,
                                       unsigned long long nb, unsigned long long &acc) {
    unsigned lo, hi;
    asm("lop3.b32 %0, %1, 0x7, 0x4B000000, 0xEA;" : "=r"(lo) : "r"(s));
    asm("lop3.b32 %0, %1, 0x38, 0x4B000000, 0xEA;" : "=r"(hi) : "r"(s));
    unsigned long long f;
    asm("mov.b64 %0, {%1, %2};" : "=l"(f) : "r"(lo), "r"(hi));
    asm("add.rn.f32x2 %0, %1, %2;" : "=l"(f) : "l"(f), "l"(nb));
    asm("fma.rn.f32x2 %0, %1, %2, %3;" : "=l"(acc) : "l"(xp), "l"(f), "l"(acc));
}

// unpack one GPTQ int3 triple (32 values) for one column.
// xpr: 15 packed x pairs (permuted layout); xb10/xb21: boundary x values.
__device__ __forceinline__ void unpack_col_p(unsigned w0, unsigned w1, unsigned w2,
                                             const unsigned long long* __restrict__ xpr,
                                             float xb10, float xb21,
                                             unsigned long long nb,
                                             unsigned long long &acc, float &accs) {
#pragma unroll
    for (int t = 0; t < 5; t++)            // v0..v9
        dqpair(w0 >> (6 * t), xpr[t], nb, acc);
    accs = fmaf(xb10, dq3(((w0 >> 30) & 3u) | ((w1 & 1u) << 2)), accs);
#pragma unroll
    for (int t = 0; t < 5; t++)            // v11..v20
        dqpair(w1 >> (6 * t + 1), xpr[5 + t], nb, acc);
    accs = fmaf(xb21, dq3(((w1 >> 31) & 1u) | ((w2 & 3u) << 1)), accs);
#pragma unroll
    for (int t = 0; t < 5; t++)            // v22..v31
        dqpair(w2 >> (6 * t + 2), xpr[10 + t], nb, acc);
}

__global__ __launch_bounds__(TPB)
void q3_fused_kernel(const float* __restrict__ x, const unsigned* __restrict__ qw,
                     const float* __restrict__ scales,
                     const float* __restrict__ zeros,
                     const float* __restrict__ bias,
                     float* __restrict__ y) {
    __shared__ __align__(16) float xs[GPB * 32];
    __shared__ float wsum[TPB / 32];
    __shared__ int amLast;

    const int tid = threadIdx.x;
    const int gbase = blockIdx.y * GPB;      // first group of this K-slice
    const int kbase = gbase * 32;            // first in-feature

    // stage this K-slice of x into shared: parity-scaled AND permuted so each
    // extraction pair occupies an aligned 8-byte slot.
    //   src 0..9   -> slots 0..9      (w0 pairs)
    //   src 10     -> slot 30         (boundary v10)
    //   src 11..20 -> slots 10..19    (w1 pairs)
    //   src 21     -> slot 31         (boundary v21)
    //   src 22..31 -> slots 20..29    (w2 pairs)
    for (int i = tid; i < GPB * 32; i += TPB) {
        const int s32 = i & 31, g = i >> 5;
        float v = x[kbase + i];
        if ((HI_MASK >> s32) & 1u) v *= 0.125f;
        int d;
        if (s32 == 10)      d = 30;
        else if (s32 == 21) d = 31;
        else if (s32 < 10)  d = s32;
        else if (s32 < 21)  d = s32 - 1;
        else                d = s32 - 2;
        xs[g * 32 + d] = v;
    }
    __syncthreads();

    const int c = blockIdx.x * COLS_PER_BLOCK + tid * COLS_PER_THREAD;
    const uint4* __restrict__ q4 = (const uint4*)qw;
    long base = (long)(gbase * 3) * ROWSTRIDE4 + (c >> 2);

    unsigned long long a0 = 0ull, a1 = 0ull, a2 = 0ull, a3 = 0ull;   // packed (f32,f32)
    float s0 = 0.f, s1 = 0.f, s2 = 0.f, s3 = 0.f;                    // boundary accs
    const unsigned long long nb = 0xCB000000CB000000ull;             // (-2^23, -2^23)

    // prologue load (group 0 of slice)
    uint4 cw0 = q4[base];
    uint4 cw1 = q4[base + ROWSTRIDE4];
    uint4 cw2 = q4[base + 2 * ROWSTRIDE4];

#pragma unroll 1
    for (int g = 0; g < GPB; g++) {
        uint4 nw0, nw1, nw2;
        if (g + 1 < GPB) {                   // prefetch next group while computing
            long nbs = base + (long)(3 * (g + 1)) * ROWSTRIDE4;
            nw0 = q4[nbs];
            nw1 = q4[nbs + ROWSTRIDE4];
            nw2 = q4[nbs + 2 * ROWSTRIDE4];
        }
        // pull this group's 15 packed x pairs + 2 boundary x into registers
        const unsigned long long* __restrict__ xp =
            (const unsigned long long*)&xs[g * 32];
        unsigned long long xpr[15];
#pragma unroll
        for (int t = 0; t < 15; t++) xpr[t] = xp[t];
        const float xb10 = xs[g * 32 + 30];
        const float xb21 = xs[g * 32 + 31];

        unpack_col_p(cw0.x, cw1.x, cw2.x, xpr, xb10, xb21, nb, a0, s0);
        unpack_col_p(cw0.y, cw1.y, cw2.y, xpr, xb10, xb21, nb, a1, s1);
        unpack_col_p(cw0.z, cw1.z, cw2.z, xpr, xb10, xb21, nb, a2, s2);
        unpack_col_p(cw0.w, cw1.w, cw2.w, xpr, xb10, xb21, nb, a3, s3);

        cw0 = nw0; cw1 = nw1; cw2 = nw2;
    }

    // collapse packed lanes + boundary acc (fixed order -> deterministic)
    union { unsigned long long u; float2 f; } c0, c1, c2, c3;
    c0.u = a0; c1.u = a1; c2.u = a2; c3.u = a3;
    float4 o;
    o.x = (c0.f.x + c0.f.y) + s0;
    o.y = (c1.f.x + c1.f.y) + s1;
    o.z = (c2.f.x + c2.f.y) + s2;
    o.w = (c3.f.x + c3.f.y) + s3;
    *(float4*)&g_partial[blockIdx.y * OUTF + c] = o;

    // ---- last-block-done tail reduction for this column stripe ----
    __threadfence();
    if (tid == 0) {
        int old = atomicAdd(&g_count[blockIdx.x], 1);
        amLast = (old == KS - 1);
    }
    __syncthreads();

    if (amLast) {
        // block-wide sum of x (fixed order -> deterministic, same in every stripe)
        const float4* __restrict__ x4 = (const float4*)x;
        float s = 0.f;
#pragma unroll
        for (int i = 0; i < INF / (4 * TPB); i++) {
            float4 v = x4[tid + TPB * i];
            s += (v.x + v.y) + (v.z + v.w);
        }
#pragma unroll
        for (int o2 = 16; o2 > 0; o2 >>= 1) s += __shfl_down_sync(0xffffffffu, s, o2);
        if ((tid & 31) == 0) wsum[tid >> 5] = s;
        __syncthreads();
        const float sumx = (wsum[0] + wsum[1]) + (wsum[2] + wsum[3]);

        // reduce the 64 split-K partials for this stripe in fixed k-order
        float r0 = 0.f, r1 = 0.f, r2 = 0.f, r3 = 0.f;
#pragma unroll 8
        for (int k = 0; k < KS; k++) {
            float4 p = *(const float4*)&g_partial[k * OUTF + c];
            r0 += p.x; r1 += p.y; r2 += p.z; r3 += p.w;
        }

        float4 sc = *(const float4*)&scales[c];
        float4 zr = *(const float4*)&zeros[c];
        float4 bi = *(const float4*)&bias[c];
        float4 oy;
        oy.x = sc.x * r0 - zr.x * sumx + bi.x;
        oy.y = sc.y * r1 - zr.y * sumx + bi.y;
        oy.z = sc.z * r2 - zr.z * sumx + bi.z;
        oy.w = sc.w * r3 - zr.w * sumx + bi.w;
        *(float4*)&y[c] = oy;

        if (tid == 0) g_count[blockIdx.x] = 0;   // reset for next launch/replay
    }
}

extern "C" void kernel_launch(void* const* d_in, const int* in_sizes, int n_in,
                              void* d_out, int out_size) {
    const float*    x      = (const float*)d_in[0];
    const unsigned* qw     = (const unsigned*)d_in[1];   // int32 bits -> uint32
    const float*    scales = (const float*)d_in[2];
    const float*    zeros  = (const float*)d_in[3];
    const float*    bias   = (const float*)d_in[4];
    float*          y      = (float*)d_out;

    dim3 grid(NCB, KS);
    q3_fused_kernel<<<grid, TPB>>>(x, qw, scales, zeros, bias, y);
}

// round 7
// speedup vs baseline: 1.1175x; 1.1175x over previous
#include <cuda_runtime.h>
#include <stdint.h>

#define OUTF 8192
#define INF  8192
#define GROUPS 256            // groups of 32 in-features (3 packed words each)
#define KS 32                 // split-K factor
#define GPB (GROUPS / KS)     // 8 groups per block
#define TPB 128
#define COLS_PER_THREAD 4
#define COLS_PER_BLOCK (TPB * COLS_PER_THREAD)   // 512
#define NCB (OUTF / COLS_PER_BLOCK)              // 16
#define ROWSTRIDE4 (OUTF / 4)                    // uint4 row stride

// parity mask over SOURCE index (mod 32): "hi" member of an extraction pair,
// whose x is pre-scaled by 1/8 at staging (exact power of two).
#define HI_MASK 0xAA9552AAu

// split-K partial dot products: partial[k][n] = sum over K-slice k of x*q
__device__ float g_partial[KS * OUTF];
// per-stripe completion counters (zero-init; reducer resets to 0 each launch)
__device__ int g_count[NCB];

__device__ __forceinline__ float dq3(unsigned v) {
    return __uint_as_float(0x4B000000u | v) - 8388608.0f;
}

// One extraction pair, fully packed:
//   lo = (s & 7)  | 0x4B000000   -> 2^23 + v_lo
//   hi = (s & 56) | 0x4B000000   -> 2^23 + 8*v_hi   (x_hi pre-scaled by 1/8)
// then one ADD2 (de-bias both lanes) + one FFMA2 (both products into acc).
__device__ __forceinline__ void dqpair(unsigned s, unsigned long long xp,
                                       unsigned long long nb, unsigned long long &acc) {
    unsigned lo, hi;
    asm("lop3.b32 %0, %1, 0x7, 0x4B000000, 0xEA;" : "=r"(lo) : "r"(s));
    asm("lop3.b32 %0, %1, 0x38, 0x4B000000, 0xEA;" : "=r"(hi) : "r"(s));
    unsigned long long f;
    asm("mov.b64 %0, {%1, %2};" : "=l"(f) : "r"(lo), "r"(hi));
    asm("add.rn.f32x2 %0, %1, %2;" : "=l"(f) : "l"(f), "l"(nb));
    asm("fma.rn.f32x2 %0, %1, %2, %3;" : "=l"(acc) : "l"(xp), "l"(f), "l"(acc));
}

// unpack one GPTQ int3 triple (32 values) for one column.
// xpr: 15 packed x pairs (permuted layout); xb10/xb21: boundary x values.
__device__ __forceinline__ void unpack_col_p(unsigned w0, unsigned w1, unsigned w2,
                                             const unsigned long long* __restrict__ xpr,
                                             float xb10, float xb21,
                                             unsigned long long nb,
                                             unsigned long long &acc, float &accs) {
#pragma unroll
    for (int t = 0; t < 5; t++)            // v0..v9
        dqpair(w0 >> (6 * t), xpr[t], nb, acc);
    accs = fmaf(xb10, dq3(((w0 >> 30) & 3u) | ((w1 & 1u) << 2)), accs);
#pragma unroll
    for (int t = 0; t < 5; t++)            // v11..v20
        dqpair(w1 >> (6 * t + 1), xpr[5 + t], nb, acc);
    accs = fmaf(xb21, dq3(((w1 >> 31) & 1u) | ((w2 & 3u) << 1)), accs);
#pragma unroll
    for (int t = 0; t < 5; t++)            // v22..v31
        dqpair(w2 >> (6 * t + 2), xpr[10 + t], nb, acc);
}

__global__ __launch_bounds__(TPB)
void q3_fused_kernel(const float* __restrict__ x, const unsigned* __restrict__ qw,
                     const float* __restrict__ scales,
                     const float* __restrict__ zeros,
                     const float* __restrict__ bias,
                     float* __restrict__ y) {
    __shared__ __align__(16) float xs[GPB * 32];
    __shared__ float wsum[TPB / 32];
    __shared__ int amLast;

    const int tid = threadIdx.x;
    const int gbase = blockIdx.y * GPB;      // first group of this K-slice
    const int kbase = gbase * 32;            // first in-feature

    // stage this K-slice of x into shared: parity-scaled AND permuted so each
    // extraction pair occupies an aligned 8-byte slot.
    //   src 0..9   -> slots 0..9      (w0 pairs)
    //   src 10     -> slot 30         (boundary v10)
    //   src 11..20 -> slots 10..19    (w1 pairs)
    //   src 21     -> slot 31         (boundary v21)
    //   src 22..31 -> slots 20..29    (w2 pairs)
    for (int i = tid; i < GPB * 32; i += TPB) {
        const int s32 = i & 31, g = i >> 5;
        float v = x[kbase + i];
        if ((HI_MASK >> s32) & 1u) v *= 0.125f;
        int d;
        if (s32 == 10)      d = 30;
        else if (s32 == 21) d = 31;
        else if (s32 < 10)  d = s32;
        else if (s32 < 21)  d = s32 - 1;
        else                d = s32 - 2;
        xs[g * 32 + d] = v;
    }
    __syncthreads();

    const int c = blockIdx.x * COLS_PER_BLOCK + tid * COLS_PER_THREAD;
    const uint4* __restrict__ q4 = (const uint4*)qw;
    long base = (long)(gbase * 3) * ROWSTRIDE4 + (c >> 2);

    unsigned long long a0 = 0ull, a1 = 0ull, a2 = 0ull, a3 = 0ull;   // packed (f32,f32)
    float s0 = 0.f, s1 = 0.f, s2 = 0.f, s3 = 0.f;                    // boundary accs
    const unsigned long long nb = 0xCB000000CB000000ull;             // (-2^23, -2^23)

    // ---- software pipeline, depth 2: three rotating word buffers ----
    uint4 cw[3][3];
#pragma unroll
    for (int p = 0; p < 2; p++) {
        long pb = base + (long)(3 * p) * ROWSTRIDE4;
        cw[p][0] = q4[pb];
        cw[p][1] = q4[pb + ROWSTRIDE4];
        cw[p][2] = q4[pb + 2 * ROWSTRIDE4];
    }

#pragma unroll
    for (int g = 0; g < GPB; g++) {
        const int sl = g % 3;
        if (g + 2 < GPB) {                   // prefetch 2 groups ahead
            const int psl = (g + 2) % 3;
            long nbs = base + (long)(3 * (g + 2)) * ROWSTRIDE4;
            cw[psl][0] = q4[nbs];
            cw[psl][1] = q4[nbs + ROWSTRIDE4];
            cw[psl][2] = q4[nbs + 2 * ROWSTRIDE4];
        }
        // pull this group's 15 packed x pairs + 2 boundary x into registers
        const unsigned long long* __restrict__ xp =
            (const unsigned long long*)&xs[g * 32];
        unsigned long long xpr[15];
#pragma unroll
        for (int t = 0; t < 15; t++) xpr[t] = xp[t];
        const float xb10 = xs[g * 32 + 30];
        const float xb21 = xs[g * 32 + 31];

        unpack_col_p(cw[sl][0].x, cw[sl][1].x, cw[sl][2].x, xpr, xb10, xb21, nb, a0, s0);
        unpack_col_p(cw[sl][0].y, cw[sl][1].y, cw[sl][2].y, xpr, xb10, xb21, nb, a1, s1);
        unpack_col_p(cw[sl][0].z, cw[sl][1].z, cw[sl][2].z, xpr, xb10, xb21, nb, a2, s2);
        unpack_col_p(cw[sl][0].w, cw[sl][1].w, cw[sl][2].w, xpr, xb10, xb21, nb, a3, s3);
    }

    // collapse packed lanes + boundary acc (fixed order -> deterministic)
    union { unsigned long long u; float2 f; } c0, c1, c2, c3;
    c0.u = a0; c1.u = a1; c2.u = a2; c3.u = a3;
    float4 o;
    o.x = (c0.f.x + c0.f.y) + s0;
    o.y = (c1.f.x + c1.f.y) + s1;
    o.z = (c2.f.x + c2.f.y) + s2;
    o.w = (c3.f.x + c3.f.y) + s3;
    *(float4*)&g_partial[blockIdx.y * OUTF + c] = o;

    // ---- last-block-done tail reduction for this column stripe ----
    __threadfence();
    if (tid == 0) {
        int old = atomicAdd(&g_count[blockIdx.x], 1);
        amLast = (old == KS - 1);
    }
    __syncthreads();

    if (amLast) {
        // block-wide sum of x (fixed order -> deterministic, same in every stripe)
        const float4* __restrict__ x4 = (const float4*)x;
        float s = 0.f;
#pragma unroll
        for (int i = 0; i < INF / (4 * TPB); i++) {
            float4 v = x4[tid + TPB * i];
            s += (v.x + v.y) + (v.z + v.w);
        }
#pragma unroll
        for (int o2 = 16; o2 > 0; o2 >>= 1) s += __shfl_down_sync(0xffffffffu, s, o2);
        if ((tid & 31) == 0) wsum[tid >> 5] = s;
        __syncthreads();
        const float sumx = (wsum[0] + wsum[1]) + (wsum[2] + wsum[3]);

        // reduce the 32 split-K partials for this stripe in fixed k-order
        float r0 = 0.f, r1 = 0.f, r2 = 0.f, r3 = 0.f;
#pragma unroll
        for (int k = 0; k < KS; k++) {
            float4 p = *(const float4*)&g_partial[k * OUTF + c];
            r0 += p.x; r1 += p.y; r2 += p.z; r3 += p.w;
        }

        float4 sc = *(const float4*)&scales[c];
        float4 zr = *(const float4*)&zeros[c];
        float4 bi = *(const float4*)&bias[c];
        float4 oy;
        oy.x = sc.x * r0 - zr.x * sumx + bi.x;
        oy.y = sc.y * r1 - zr.y * sumx + bi.y;
        oy.z = sc.z * r2 - zr.z * sumx + bi.z;
        oy.w = sc.w * r3 - zr.w * sumx + bi.w;
        *(float4*)&y[c] = oy;

        if (tid == 0) g_count[blockIdx.x] = 0;   // reset for next launch/replay
    }
}

extern "C" void kernel_launch(void* const* d_in, const int* in_sizes, int n_in,
                              void* d_out, int out_size) {
    const float*    x      = (const float*)d_in[0];
    const unsigned* qw     = (const unsigned*)d_in[1];   // int32 bits -> uint32
    const float*    scales = (const float*)d_in[2];
    const float*    zeros  = (const float*)d_in[3];
    const float*    bias   = (const float*)d_in[4];
    float*          y      = (float*)d_out;

    dim3 grid(NCB, KS);
    q3_fused_kernel<<<grid, TPB>>>(x, qw, scales, zeros, bias, y);
}

// round 8
// speedup vs baseline: 1.1345x; 1.0152x over previous
#include <cuda_runtime.h>
#include <stdint.h>

#define OUTF 8192
#define INF  8192
#define GROUPS 256            // groups of 32 in-features (3 packed words each)
#define KS 32                 // split-K factor
#define GPB (GROUPS / KS)     // 8 groups per block
#define TPB 128
#define COLS_PER_THREAD 2
#define COLS_PER_BLOCK (TPB * COLS_PER_THREAD)   // 256
#define NCB (OUTF / COLS_PER_BLOCK)              // 32
#define ROWSTRIDE2 (OUTF / 2)                    // uint2 row stride

// parity mask over SOURCE index (mod 32): "hi" member of an extraction pair,
// whose x is pre-scaled by 1/8 at staging (exact power of two).
#define HI_MASK 0xAA9552AAu

// split-K partial dot products: partial[k][n] = sum over K-slice k of x*q
__device__ float g_partial[KS * OUTF];
// per-stripe completion counters (zero-init; reducer resets to 0 each launch)
__device__ int g_count[NCB];

__device__ __forceinline__ float dq3(unsigned v) {
    return __uint_as_float(0x4B000000u | v) - 8388608.0f;
}

// One extraction pair, fully packed:
//   lo = (s & 7)  | 0x4B000000   -> 2^23 + v_lo
//   hi = (s & 56) | 0x4B000000   -> 2^23 + 8*v_hi   (x_hi pre-scaled by 1/8)
// then one ADD2 (de-bias both lanes) + one FFMA2 (both products into acc).
__device__ __forceinline__ void dqpair(unsigned s, unsigned long long xp,
                                       unsigned long long nb, unsigned long long &acc) {
    unsigned lo, hi;
    asm("lop3.b32 %0, %1, 0x7, 0x4B000000, 0xEA;" : "=r"(lo) : "r"(s));
    asm("lop3.b32 %0, %1, 0x38, 0x4B000000, 0xEA;" : "=r"(hi) : "r"(s));
    unsigned long long f;
    asm("mov.b64 %0, {%1, %2};" : "=l"(f) : "r"(lo), "r"(hi));
    asm("add.rn.f32x2 %0, %1, %2;" : "=l"(f) : "l"(f), "l"(nb));
    asm("fma.rn.f32x2 %0, %1, %2, %3;" : "=l"(acc) : "l"(xp), "l"(f), "l"(acc));
}

// unpack one GPTQ int3 triple (32 values) for one column.
// xpr: 15 packed x pairs (permuted layout); xb10/xb21: boundary x values.
__device__ __forceinline__ void unpack_col_p(unsigned w0, unsigned w1, unsigned w2,
                                             const unsigned long long* __restrict__ xpr,
                                             float xb10, float xb21,
                                             unsigned long long nb,
                                             unsigned long long &acc, float &accs) {
#pragma unroll
    for (int t = 0; t < 5; t++)            // v0..v9
        dqpair(w0 >> (6 * t), xpr[t], nb, acc);
    accs = fmaf(xb10, dq3(((w0 >> 30) & 3u) | ((w1 & 1u) << 2)), accs);
#pragma unroll
    for (int t = 0; t < 5; t++)            // v11..v20
        dqpair(w1 >> (6 * t + 1), xpr[5 + t], nb, acc);
    accs = fmaf(xb21, dq3(((w1 >> 31) & 1u) | ((w2 & 3u) << 1)), accs);
#pragma unroll
    for (int t = 0; t < 5; t++)            // v22..v31
        dqpair(w2 >> (6 * t + 2), xpr[10 + t], nb, acc);
}

__global__ __launch_bounds__(TPB)
void q3_fused_kernel(const float* __restrict__ x, const unsigned* __restrict__ qw,
                     const float* __restrict__ scales,
                     const float* __restrict__ zeros,
                     const float* __restrict__ bias,
                     float* __restrict__ y) {
    __shared__ __align__(16) float xs[GPB * 32];
    __shared__ float wsum[TPB / 32];
    __shared__ int amLast;

    const int tid = threadIdx.x;
    const int gbase = blockIdx.y * GPB;      // first group of this K-slice
    const int kbase = gbase * 32;            // first in-feature

    // stage this K-slice of x into shared: parity-scaled AND permuted so each
    // extraction pair occupies an aligned 8-byte slot.
    //   src 0..9   -> slots 0..9      (w0 pairs)
    //   src 10     -> slot 30         (boundary v10)
    //   src 11..20 -> slots 10..19    (w1 pairs)
    //   src 21     -> slot 31         (boundary v21)
    //   src 22..31 -> slots 20..29    (w2 pairs)
    for (int i = tid; i < GPB * 32; i += TPB) {
        const int s32 = i & 31, g = i >> 5;
        float v = x[kbase + i];
        if ((HI_MASK >> s32) & 1u) v *= 0.125f;
        int d;
        if (s32 == 10)      d = 30;
        else if (s32 == 21) d = 31;
        else if (s32 < 10)  d = s32;
        else if (s32 < 21)  d = s32 - 1;
        else                d = s32 - 2;
        xs[g * 32 + d] = v;
    }
    __syncthreads();

    const int c = blockIdx.x * COLS_PER_BLOCK + tid * COLS_PER_THREAD;
    const uint2* __restrict__ q2 = (const uint2*)qw;
    long base = (long)(gbase * 3) * ROWSTRIDE2 + (c >> 1);

    unsigned long long a0 = 0ull, a1 = 0ull;     // packed (f32,f32) accumulators
    float s0 = 0.f, s1 = 0.f;                    // boundary accs
    const unsigned long long nb = 0xCB000000CB000000ull;   // (-2^23, -2^23)

    // ---- software pipeline, depth 2: three rotating word buffers ----
    uint2 cw[3][3];
#pragma unroll
    for (int p = 0; p < 2; p++) {
        long pb = base + (long)(3 * p) * ROWSTRIDE2;
        cw[p][0] = q2[pb];
        cw[p][1] = q2[pb + ROWSTRIDE2];
        cw[p][2] = q2[pb + 2 * ROWSTRIDE2];
    }

#pragma unroll
    for (int g = 0; g < GPB; g++) {
        const int sl = g % 3;
        if (g + 2 < GPB) {                   // prefetch 2 groups ahead
            const int psl = (g + 2) % 3;
            long nbs = base + (long)(3 * (g + 2)) * ROWSTRIDE2;
            cw[psl][0] = q2[nbs];
            cw[psl][1] = q2[nbs + ROWSTRIDE2];
            cw[psl][2] = q2[nbs + 2 * ROWSTRIDE2];
        }
        // pull this group's 15 packed x pairs + 2 boundary x into registers
        const unsigned long long* __restrict__ xp =
            (const unsigned long long*)&xs[g * 32];
        unsigned long long xpr[15];
#pragma unroll
        for (int t = 0; t < 15; t++) xpr[t] = xp[t];
        const float xb10 = xs[g * 32 + 30];
        const float xb21 = xs[g * 32 + 31];

        unpack_col_p(cw[sl][0].x, cw[sl][1].x, cw[sl][2].x, xpr, xb10, xb21, nb, a0, s0);
        unpack_col_p(cw[sl][0].y, cw[sl][1].y, cw[sl][2].y, xpr, xb10, xb21, nb, a1, s1);
    }

    // collapse packed lanes + boundary acc (fixed order -> deterministic)
    union { unsigned long long u; float2 f; } c0, c1;
    c0.u = a0; c1.u = a1;
    float2 o;
    o.x = (c0.f.x + c0.f.y) + s0;
    o.y = (c1.f.x + c1.f.y) + s1;
    *(float2*)&g_partial[blockIdx.y * OUTF + c] = o;

    // ---- last-block-done tail reduction for this column stripe ----
    __threadfence();
    if (tid == 0) {
        int old = atomicAdd(&g_count[blockIdx.x], 1);
        amLast = (old == KS - 1);
    }
    __syncthreads();

    if (amLast) {
        // block-wide sum of x (fixed order -> deterministic, same in every stripe)
        const float4* __restrict__ x4 = (const float4*)x;
        float s = 0.f;
#pragma unroll
        for (int i = 0; i < INF / (4 * TPB); i++) {
            float4 v = x4[tid + TPB * i];
            s += (v.x + v.y) + (v.z + v.w);
        }
#pragma unroll
        for (int o2 = 16; o2 > 0; o2 >>= 1) s += __shfl_down_sync(0xffffffffu, s, o2);
        if ((tid & 31) == 0) wsum[tid >> 5] = s;
        __syncthreads();
        const float sumx = (wsum[0] + wsum[1]) + (wsum[2] + wsum[3]);

        // reduce the 32 split-K partials for this stripe in fixed k-order
        float r0 = 0.f, r1 = 0.f;
#pragma unroll
        for (int k = 0; k < KS; k++) {
            float2 p = *(const float2*)&g_partial[k * OUTF + c];
            r0 += p.x; r1 += p.y;
        }

        float2 sc = *(const float2*)&scales[c];
        float2 zr = *(const float2*)&zeros[c];
        float2 bi = *(const float2*)&bias[c];
        float2 oy;
        oy.x = sc.x * r0 - zr.x * sumx + bi.x;
        oy.y = sc.y * r1 - zr.y * sumx + bi.y;
        *(float2*)&y[c] = oy;

        if (tid == 0) g_count[blockIdx.x] = 0;   // reset for next launch/replay
    }
}

extern "C" void kernel_launch(void* const* d_in, const int* in_sizes, int n_in,
                              void* d_out, int out_size) {
    const float*    x      = (const float*)d_in[0];
    const unsigned* qw     = (const unsigned*)d_in[1];   // int32 bits -> uint32
    const float*    scales = (const float*)d_in[2];
    const float*    zeros  = (const float*)d_in[3];
    const float*    bias   = (const float*)d_in[4];
    float*          y      = (float*)d_out;

    dim3 grid(NCB, KS);
    q3_fused_kernel<<<grid, TPB>>>(x, qw, scales, zeros, bias, y);
}

// round 9
// speedup vs baseline: 1.2937x; 1.1404x over previous
#include <cuda_runtime.h>
#include <stdint.h>

#define OUTF 8192
#define INF  8192
#define GROUPS 256            // groups of 32 in-features (3 packed words each)
#define KS 32                 // split-K factor
#define GPB (GROUPS / KS)     // 8 groups per block
#define TPB 128
#define COLS_PER_THREAD 2
#define COLS_PER_BLOCK (TPB * COLS_PER_THREAD)   // 256
#define NCB (OUTF / COLS_PER_BLOCK)              // 32
#define ROWSTRIDE2 (OUTF / 2)                    // uint2 row stride
#define SLOTS 34                                  // 17 packed x pairs per group

// split-K partial dot products: partial[k][n] = sum over K-slice k of x*q
__device__ float g_partial[KS * OUTF];
// per-stripe completion counters (zero-init; reducer resets to 0 each launch)
__device__ int g_count[NCB];

// One extraction pair, shift-free:
//   lo = (a & AM) | 0x4B000000  -> 2^23 + v_lo * 2^b_lo   (in-place field)
//   hi = (b & BM) | 0x4B000000  -> 2^23 + v_hi * 2^b_hi
// x slots are pre-scaled by 2^-b at staging (exact), so after one packed
// de-bias (ADD2) a single FFMA2 accumulates both exact products.
template <unsigned AM, unsigned BM>
__device__ __forceinline__ void dqpm(unsigned a, unsigned b, unsigned long long xp,
                                     unsigned long long nb, unsigned long long &acc) {
    unsigned lo, hi;
    asm("lop3.b32 %0, %1, %2, 0x4B000000, 0xEA;" : "=r"(lo) : "r"(a), "n"(AM));
    asm("lop3.b32 %0, %1, %2, 0x4B000000, 0xEA;" : "=r"(hi) : "r"(b), "n"(BM));
    unsigned long long f;
    asm("mov.b64 %0, {%1, %2};" : "=l"(f) : "r"(lo), "r"(hi));
    asm("add.rn.f32x2 %0, %1, %2;" : "=l"(f) : "l"(f), "l"(nb));
    asm("fma.rn.f32x2 %0, %1, %2, %3;" : "=l"(acc) : "l"(xp), "l"(f), "l"(acc));
}

// unpack one GPTQ int3 triple (32 values) for one column; 17 packed pairs,
// alternating between two accumulator chains for ILP.
__device__ __forceinline__ void unpack_col_m(unsigned w0, unsigned w1, unsigned w2,
                                             const unsigned long long* __restrict__ xpr,
                                             unsigned long long nb,
                                             unsigned long long &accA, unsigned long long &accB) {
    const unsigned s0 = w0 >> 16, s1 = w1 >> 16, s2 = w2 >> 16;
    // w0: v0..v9 at bits 0,3,...,27 (bits >20 via s0)
    dqpm<(0x7u),      (0x7u << 3)> (w0, w0, xpr[0],  nb, accA);
    dqpm<(0x7u << 6), (0x7u << 9)> (w0, w0, xpr[1],  nb, accB);
    dqpm<(0x7u << 12),(0x7u << 15)>(w0, w0, xpr[2],  nb, accA);
    dqpm<(0x7u << 18),(0x7u << 5)> (w0, s0, xpr[3],  nb, accB);
    dqpm<(0x7u << 8), (0x7u << 11)>(s0, s0, xpr[4],  nb, accA);
    // w1: v11..v20 at bits 1,4,...,28 (bits >20 via s1)
    dqpm<(0x7u << 1), (0x7u << 4)> (w1, w1, xpr[5],  nb, accB);
    dqpm<(0x7u << 7), (0x7u << 10)>(w1, w1, xpr[6],  nb, accA);
    dqpm<(0x7u << 13),(0x7u << 16)>(w1, w1, xpr[7],  nb, accB);
    dqpm<(0x7u << 19),(0x7u << 6)> (w1, s1, xpr[8],  nb, accA);
    dqpm<(0x7u << 9), (0x7u << 12)>(s1, s1, xpr[9],  nb, accB);
    // w2: v22..v31 at bits 2,5,...,29 (bits >20 via s2)
    dqpm<(0x7u << 2), (0x7u << 5)> (w2, w2, xpr[10], nb, accA);
    dqpm<(0x7u << 8), (0x7u << 11)>(w2, w2, xpr[11], nb, accB);
    dqpm<(0x7u << 14),(0x7u << 17)>(w2, w2, xpr[12], nb, accA);
    dqpm<(0x7u << 20),(0x7u << 7)> (w2, s2, xpr[13], nb, accB);
    dqpm<(0x7u << 10),(0x7u << 13)>(s2, s2, xpr[14], nb, accA);
    // boundary v10: low2 = w0 bits30-31 (via s0 @14, weight 1), hi = w1 bit0 (weight 4)
    dqpm<(0x3u << 14),(0x1u)>      (s0, w1, xpr[15], nb, accB);
    // boundary v21: lo = w1 bit31 (via s1 @15, weight 1), low2 = w2 bits0-1 (weight 2)
    dqpm<(0x1u << 15),(0x3u)>      (s1, w2, xpr[16], nb, accA);
}

__global__ __launch_bounds__(TPB, 7)
void q3_fused_kernel(const float* __restrict__ x, const unsigned* __restrict__ qw,
                     const float* __restrict__ scales,
                     const float* __restrict__ zeros,
                     const float* __restrict__ bias,
                     float* __restrict__ y) {
    __shared__ __align__(8) float xs[GPB * SLOTS];
    __shared__ float wsum[TPB / 32];
    __shared__ int amLast;

    const int tid = threadIdx.x;
    const int gbase = blockIdx.y * GPB;      // first group of this K-slice
    const int kbase = gbase * 32;            // first in-feature

    // Stage x pairs: slot d of each group holds x[j] * 2^e, where the packed
    // field for that slot is v * 2^b (b = in-word bit position, or b-16 when
    // extracted from w>>16). e = (b<=20) ? -b : 16-b. Exact power-of-two
    // scaling; products in the mainloop round identically to x*v.
    for (int i = tid; i < GPB * SLOTS; i += TPB) {
        const int d = i % SLOTS, g = i / SLOTS;
        int j, b;
        if (d < 10)       { j = d;     b = 3 * d; }
        else if (d < 20)  { j = d + 1; b = 3 * d - 29; }
        else if (d < 30)  { j = d + 2; b = 3 * d - 58; }
        else if (d == 30) { j = 10;    b = 30; }    // v10 low2 via s0@14 -> e=-14
        else if (d == 31) { j = 10;    b = -2; }    // v10 hi bit, weight 4 -> e=+2
        else if (d == 32) { j = 21;    b = 31; }    // v21 bit via s1@15 -> e=-15
        else              { j = 21;    b = -1; }    // v21 low2, weight 2 -> e=+1
        const int e = (b <= 20) ? -b : 16 - b;
        const float sc = __uint_as_float((unsigned)(127 + e) << 23);
        xs[g * SLOTS + d] = x[kbase + g * 32 + j] * sc;
    }
    __syncthreads();

    const int c = blockIdx.x * COLS_PER_BLOCK + tid * COLS_PER_THREAD;
    const uint2* __restrict__ q2 = (const uint2*)qw;
    long base = (long)(gbase * 3) * ROWSTRIDE2 + (c >> 1);

    // packed (f32,f32) accumulators: 2 chains per column
    unsigned long long a0A = 0ull, a0B = 0ull, a1A = 0ull, a1B = 0ull;
    const unsigned long long nb = 0xCB000000CB000000ull;   // (-2^23, -2^23)

    // prologue load (group 0 of slice)
    uint2 cw0 = q2[base];
    uint2 cw1 = q2[base + ROWSTRIDE2];
    uint2 cw2 = q2[base + 2 * ROWSTRIDE2];

#pragma unroll
    for (int g = 0; g < GPB; g++) {
        uint2 nw0, nw1, nw2;
        if (g + 1 < GPB) {                   // prefetch next group while computing
            long nbs = base + (long)(3 * (g + 1)) * ROWSTRIDE2;
            nw0 = q2[nbs];
            nw1 = q2[nbs + ROWSTRIDE2];
            nw2 = q2[nbs + 2 * ROWSTRIDE2];
        }
        // this group's 17 packed x pairs -> registers, shared by both columns
        const unsigned long long* __restrict__ xp =
            (const unsigned long long*)&xs[g * SLOTS];
        unsigned long long xpr[17];
#pragma unroll
        for (int t = 0; t < 17; t++) xpr[t] = xp[t];

        unpack_col_m(cw0.x, cw1.x, cw2.x, xpr, nb, a0A, a0B);
        unpack_col_m(cw0.y, cw1.y, cw2.y, xpr, nb, a1A, a1B);

        cw0 = nw0; cw1 = nw1; cw2 = nw2;
    }

    // collapse chains + packed lanes (fixed order -> deterministic)
    unsigned long long t0, t1;
    asm("add.rn.f32x2 %0, %1, %2;" : "=l"(t0) : "l"(a0A), "l"(a0B));
    asm("add.rn.f32x2 %0, %1, %2;" : "=l"(t1) : "l"(a1A), "l"(a1B));
    union { unsigned long long u; float2 f; } c0, c1;
    c0.u = t0; c1.u = t1;
    float2 o;
    o.x = c0.f.x + c0.f.y;
    o.y = c1.f.x + c1.f.y;
    *(float2*)&g_partial[blockIdx.y * OUTF + c] = o;

    // ---- last-block-done tail reduction for this column stripe ----
    __threadfence();
    if (tid == 0) {
        int old = atomicAdd(&g_count[blockIdx.x], 1);
        amLast = (old == KS - 1);
    }
    __syncthreads();

    if (amLast) {
        // block-wide sum of x (fixed order -> deterministic, same in every stripe)
        const float4* __restrict__ x4 = (const float4*)x;
        float s = 0.f;
#pragma unroll
        for (int i = 0; i < INF / (4 * TPB); i++) {
            float4 v = x4[tid + TPB * i];
            s += (v.x + v.y) + (v.z + v.w);
        }
#pragma unroll
        for (int o2 = 16; o2 > 0; o2 >>= 1) s += __shfl_down_sync(0xffffffffu, s, o2);
        if ((tid & 31) == 0) wsum[tid >> 5] = s;
        __syncthreads();
        const float sumx = (wsum[0] + wsum[1]) + (wsum[2] + wsum[3]);

        // reduce the 32 split-K partials for this stripe in fixed k-order
        float r0 = 0.f, r1 = 0.f;
#pragma unroll
        for (int k = 0; k < KS; k++) {
            float2 p = *(const float2*)&g_partial[k * OUTF + c];
            r0 += p.x; r1 += p.y;
        }

        float2 sc = *(const float2*)&scales[c];
        float2 zr = *(const float2*)&zeros[c];
        float2 bi = *(const float2*)&bias[c];
        float2 oy;
        oy.x = sc.x * r0 - zr.x * sumx + bi.x;
        oy.y = sc.y * r1 - zr.y * sumx + bi.y;
        *(float2*)&y[c] = oy;

        if (tid == 0) g_count[blockIdx.x] = 0;   // reset for next launch/replay
    }
}

extern "C" void kernel_launch(void* const* d_in, const int* in_sizes, int n_in,
                              void* d_out, int out_size) {
    const float*    x      = (const float*)d_in[0];
    const unsigned* qw     = (const unsigned*)d_in[1];   // int32 bits -> uint32
    const float*    scales = (const float*)d_in[2];
    const float*    zeros  = (const float*)d_in[3];
    const float*    bias   = (const float*)d_in[4];
    float*          y      = (float*)d_out;

    dim3 grid(NCB, KS);
    q3_fused_kernel<<<grid, TPB>>>(x, qw, scales, zeros, bias, y);
}